// round 9
// baseline (speedup 1.0000x reference)
#include <cuda_runtime.h>
#include <cuda_fp16.h>
#include <cstdint>

// ============================================================================
// out[8192,4096] = x[8192,4096] @ W[4096(k),4096(n)] + b
// sm_103 base-ISA: cp.async 4-stage + ldmatrix + mma.sync.m16n8k16 (fp32 acc)
// R9: persistent CTAs (grid = #SMs). Flat slab loop: the cp.async ring never
//     drains across tile boundaries; epilogue overlaps next tile's loads.
//     Inner loop identical to R5/R8 (577us GEMM, tensor 78.4%).
// ============================================================================

static constexpr int BATCH = 8192;
static constexpr int IN_F  = 4096;   // K
static constexpr int OUT_F = 4096;   // N

static constexpr int TM = 128;
static constexpr int TN = 256;
static constexpr int KS = 64;              // K per stage (128B rows)
static constexpr int NK = IN_F / KS;       // 64 slabs per tile
static constexpr int NTILES = (BATCH / TM) * (OUT_F / TN);   // 1024
static constexpr int STAGES = 4;

static constexpr uint32_t A_ST = TM * 128u;                 // 16 KB
static constexpr uint32_t B_ST = TN * 128u;                 // 32 KB
static constexpr uint32_t STAGE = A_ST + B_ST;              // 48 KB
static constexpr uint32_t SMEM_BYTES = 1024u + STAGES * STAGE;

__device__ __align__(128) __half g_xh[(size_t)BATCH * IN_F];  // x fp16 [M,K]
__device__ __align__(128) __half g_wt[(size_t)OUT_F * IN_F];  // W^T fp16 [N,K]

// ----------------------------------------------------------------------------
__device__ __forceinline__ uint32_t smem_u32(const void* p) {
    uint32_t a;
    asm("{ .reg .u64 t; cvta.to.shared.u64 t, %1; cvt.u32.u64 %0, t; }" : "=r"(a) : "l"(p));
    return a;
}
__device__ __forceinline__ uint32_t sw128(uint32_t off) {
    return off ^ ((off >> 3) & 0x70u);
}
__device__ __forceinline__ void cp16(uint32_t s, const void* g) {
    asm volatile("cp.async.cg.shared.global [%0], [%1], 16;" :: "r"(s), "l"(g));
}
__device__ __forceinline__ void ldsm4(uint32_t& r0, uint32_t& r1, uint32_t& r2, uint32_t& r3,
                                      uint32_t addr) {
    asm volatile("ldmatrix.sync.aligned.m8n8.x4.shared.b16 {%0,%1,%2,%3}, [%4];"
                 : "=r"(r0), "=r"(r1), "=r"(r2), "=r"(r3) : "r"(addr));
}
__device__ __forceinline__ void mma16816(float& c0, float& c1, float& c2, float& c3,
                                         uint32_t a0, uint32_t a1, uint32_t a2, uint32_t a3,
                                         uint32_t b0, uint32_t b1) {
    asm volatile(
        "mma.sync.aligned.m16n8k16.row.col.f32.f16.f16.f32 "
        "{%0,%1,%2,%3}, {%4,%5,%6,%7}, {%8,%9}, {%0,%1,%2,%3};"
        : "+f"(c0), "+f"(c1), "+f"(c2), "+f"(c3)
        : "r"(a0), "r"(a1), "r"(a2), "r"(a3), "r"(b0), "r"(b1));
}

// ----------------------------------------------------------------------------
// Fused preprocessing (unchanged from R8: 64x64 W transpose, streaming x cvt)
// ----------------------------------------------------------------------------
static constexpr int W_BLOCKS = (OUT_F / 64) * (IN_F / 64);   // 4096
static constexpr int X_BLOCKS = 4096;

__global__ void __launch_bounds__(256)
cvt_fused_kernel(const float* __restrict__ x, const float* __restrict__ w) {
    const int bid = blockIdx.x;
    if (bid < W_BLOCKS) {
        __shared__ __half tile[64][66];
        const int bx = bid & ((OUT_F / 64) - 1);
        const int by = bid >> 6;
        const int i0 = by * 64;
        const int o0 = bx * 64;
        const int tc = threadIdx.x & 63;
        const int tr = threadIdx.x >> 6;
        #pragma unroll
        for (int r = 0; r < 16; r++) {
            const int i = tr + r * 4;
            tile[i][tc] = __float2half(w[(size_t)(i0 + i) * OUT_F + o0 + tc]);
        }
        __syncthreads();
        #pragma unroll
        for (int r = 0; r < 16; r++) {
            const int o = tr + r * 4;
            g_wt[(size_t)(o0 + o) * IN_F + i0 + tc] = tile[tc][o];
        }
    } else {
        const size_t n8 = (size_t)BATCH * IN_F / 8;
        const size_t stride = (size_t)X_BLOCKS * 256;
        for (size_t i = (size_t)(bid - W_BLOCKS) * 256 + threadIdx.x; i < n8; i += stride) {
            float4 a = ((const float4*)x)[2 * i];
            float4 c = ((const float4*)x)[2 * i + 1];
            __half2 h0 = __floats2half2_rn(a.x, a.y);
            __half2 h1 = __floats2half2_rn(a.z, a.w);
            __half2 h2 = __floats2half2_rn(c.x, c.y);
            __half2 h3 = __floats2half2_rn(c.z, c.w);
            uint4 o;
            o.x = *reinterpret_cast<uint32_t*>(&h0);
            o.y = *reinterpret_cast<uint32_t*>(&h1);
            o.z = *reinterpret_cast<uint32_t*>(&h2);
            o.w = *reinterpret_cast<uint32_t*>(&h3);
            ((uint4*)g_xh)[i] = o;
        }
    }
}

// ----------------------------------------------------------------------------
// Persistent GEMM: grid = #SMs, each CTA walks tiles bid, bid+grid, ...
// Inner pipeline identical to R8. Slab s (global) -> tile bid+(s>>6)*grid,
// k-slab s&63. Load cursor = s+3, ring never drains at tile boundaries.
// ----------------------------------------------------------------------------
__device__ __forceinline__ void slab_ptrs(int s, int bid, int gdim,
                                          const __half*& a, const __half*& b) {
    const int t = bid + (s >> 6) * gdim;
    a = g_xh + (size_t)(t >> 4) * TM * IN_F + (size_t)(s & 63) * KS;
    b = g_wt + (size_t)(t & 15) * TN * IN_F + (size_t)(s & 63) * KS;
}

__device__ __forceinline__ void load_chunk(uint32_t st, int tid,
                                           const __half* a, const __half* b, int q) {
    if (q < 4) {
        int id = tid + (q << 8);
        int row = id >> 3;
        int c = id & 7;
        uint32_t sw = sw128(((uint32_t)row << 7) | ((uint32_t)c << 4));
        cp16(st + sw, a + (size_t)row * IN_F + (c << 3));
    } else {
        int id = tid + ((q - 4) << 8);
        int row = id >> 3;
        int c = id & 7;
        uint32_t sw = sw128(((uint32_t)row << 7) | ((uint32_t)c << 4));
        cp16(st + A_ST + sw, b + (size_t)row * IN_F + (c << 3));
    }
}

__global__ void __launch_bounds__(256, 1)
gemm_hmma_kernel(const float* __restrict__ bias, float* __restrict__ out) {
    extern __shared__ char smem_raw[];
    const uint32_t S0 = (smem_u32(smem_raw) + 1023u) & ~1023u;

    const int tid  = threadIdx.x;
    const int wid  = tid >> 5;
    const int lane = tid & 31;
    const int wm   = wid & 1;
    const int wn   = wid >> 1;
    const int bid  = blockIdx.x;
    const int gdim = gridDim.x;

    const int nt = (NTILES - bid + gdim - 1) / gdim;   // tiles for this CTA (>=1)
    const int total = nt * NK;

    const uint32_t a_row  = (uint32_t)(wm * 64 + (lane & 15));
    const uint32_t a_colb = (uint32_t)((lane >> 4) << 4);
    const uint32_t b_row  = (uint32_t)(wn * 64 + ((lane >> 4) << 3) + (lane & 7));
    const uint32_t b_colb = (uint32_t)(((lane >> 3) & 1) << 4);

    float acc[4][8][4];
    #pragma unroll
    for (int t = 0; t < 4; t++)
        #pragma unroll
        for (int j = 0; j < 8; j++)
            #pragma unroll
            for (int q = 0; q < 4; q++) acc[t][j][q] = 0.0f;

    // Prologue: fill stages with slabs 0..2
    #pragma unroll
    for (int p = 0; p < STAGES - 1; p++) {
        const __half *pa, *pb;
        slab_ptrs(p, bid, gdim, pa, pb);
        #pragma unroll
        for (int q = 0; q < 12; q++) load_chunk(S0 + (uint32_t)p * STAGE, tid, pa, pb, q);
        asm volatile("cp.async.commit_group;" ::: "memory");
    }
    asm volatile("cp.async.wait_group 1;" ::: "memory");   // slabs 0,1 complete
    __syncthreads();

    uint32_t af[2][4][4], bf[2][4][4];

    // Preload slab 0 / kk=0 fragments into buffer 0
    #pragma unroll
    for (int t = 0; t < 4; t++) {
        uint32_t off = (a_row + t * 16u) * 128u + a_colb;
        ldsm4(af[0][t][0], af[0][t][1], af[0][t][2], af[0][t][3], S0 + sw128(off));
    }
    #pragma unroll
    for (int p = 0; p < 4; p++) {
        uint32_t off = (b_row + p * 16u) * 128u + b_colb;
        ldsm4(bf[0][p][0], bf[0][p][1], bf[0][p][2], bf[0][p][3], S0 + A_ST + sw128(off));
    }

    for (int s = 0; s < total; ++s) {
        const uint32_t stA = S0 + (uint32_t)(s % STAGES) * STAGE;
        const uint32_t stB = stA + A_ST;
        const uint32_t stNext = S0 + (uint32_t)((s + 1) % STAGES) * STAGE;
        const bool last = (s == total - 1);

        const int j = s + (STAGES - 1);
        const bool doload = (j < total);
        const uint32_t stJ = S0 + (uint32_t)(j % STAGES) * STAGE;
        const __half *nA = nullptr, *nB = nullptr;
        if (doload) slab_ptrs(j, bid, gdim, nA, nB);

        #pragma unroll
        for (int kk = 0; kk < 4; kk++) {
            const int cur = kk & 1;
            const int nxt = cur ^ 1;
            // prefetch fragments: kk+1 of this slab, or kk=0 of the NEXT slab at kk=3
            if (kk < 3) {
                const uint32_t kc = (uint32_t)((kk + 1) * 32);
                #pragma unroll
                for (int t = 0; t < 4; t++) {
                    uint32_t off = (a_row + t * 16u) * 128u + kc + a_colb;
                    ldsm4(af[nxt][t][0], af[nxt][t][1], af[nxt][t][2], af[nxt][t][3],
                          stA + sw128(off));
                }
                #pragma unroll
                for (int p = 0; p < 4; p++) {
                    uint32_t off = (b_row + p * 16u) * 128u + kc + b_colb;
                    ldsm4(bf[nxt][p][0], bf[nxt][p][1], bf[nxt][p][2], bf[nxt][p][3],
                          stB + sw128(off));
                }
            } else if (!last) {
                #pragma unroll
                for (int t = 0; t < 4; t++) {
                    uint32_t off = (a_row + t * 16u) * 128u + a_colb;
                    ldsm4(af[nxt][t][0], af[nxt][t][1], af[nxt][t][2], af[nxt][t][3],
                          stNext + sw128(off));
                }
                #pragma unroll
                for (int p = 0; p < 4; p++) {
                    uint32_t off = (b_row + p * 16u) * 128u + b_colb;
                    ldsm4(bf[nxt][p][0], bf[nxt][p][1], bf[nxt][p][2], bf[nxt][p][3],
                          stNext + A_ST + sw128(off));
                }
            }
            // spread next-slab global loads: 3 chunks per kk
            if (doload) {
                #pragma unroll
                for (int c = 0; c < 3; c++) load_chunk(stJ, tid, nA, nB, kk * 3 + c);
            }
            // 32 MMAs on current fragments
            #pragma unroll
            for (int t = 0; t < 4; t++) {
                #pragma unroll
                for (int p = 0; p < 4; p++) {
                    mma16816(acc[t][2*p][0], acc[t][2*p][1], acc[t][2*p][2], acc[t][2*p][3],
                             af[cur][t][0], af[cur][t][1], af[cur][t][2], af[cur][t][3],
                             bf[cur][p][0], bf[cur][p][1]);
                    mma16816(acc[t][2*p+1][0], acc[t][2*p+1][1], acc[t][2*p+1][2], acc[t][2*p+1][3],
                             af[cur][t][0], af[cur][t][1], af[cur][t][2], af[cur][t][3],
                             bf[cur][p][2], bf[cur][p][3]);
                }
            }
        }
        asm volatile("cp.async.commit_group;" ::: "memory");

        // Tile boundary: dump accumulators (overlaps with in-flight cp.async)
        if ((s & (NK - 1)) == NK - 1) {
            const int t_idx  = bid + (s >> 6) * gdim;
            const int tile_m = t_idx >> 4;
            const int tile_n = t_idx & 15;
            const int n_base = tile_n * TN + wn * 64 + (lane & 3) * 2;
            const int m_base = tile_m * TM + wm * 64 + (lane >> 2);
            #pragma unroll
            for (int t = 0; t < 4; t++) {
                float* r0 = out + (size_t)(m_base + t * 16) * OUT_F + n_base;
                float* r1 = r0 + 8 * OUT_F;
                #pragma unroll
                for (int jj = 0; jj < 8; jj++) {
                    const float2 bv = *(const float2*)(bias + n_base + jj * 8);
                    float2 v0 = make_float2(acc[t][jj][0] + bv.x, acc[t][jj][1] + bv.y);
                    float2 v1 = make_float2(acc[t][jj][2] + bv.x, acc[t][jj][3] + bv.y);
                    *(float2*)(r0 + jj * 8) = v0;
                    *(float2*)(r1 + jj * 8) = v1;
                    acc[t][jj][0] = 0.0f; acc[t][jj][1] = 0.0f;
                    acc[t][jj][2] = 0.0f; acc[t][jj][3] = 0.0f;
                }
            }
        }

        if (!last) {
            asm volatile("cp.async.wait_group 1;" ::: "memory");
            __syncthreads();
        }
    }
}

// ----------------------------------------------------------------------------
extern "C" void kernel_launch(void* const* d_in, const int* in_sizes, int n_in,
                              void* d_out, int out_size) {
    (void)in_sizes; (void)n_in; (void)out_size;
    const float* x = (const float*)d_in[0];
    const float* w = (const float*)d_in[1];
    const float* b = (const float*)d_in[2];
    float* out = (float*)d_out;

    cvt_fused_kernel<<<W_BLOCKS + X_BLOCKS, 256>>>(x, w);

    int sms = 0;
    cudaDeviceGetAttribute(&sms, cudaDevAttrMultiProcessorCount, 0);
    if (sms <= 0) sms = 148;
    const int grid = sms < NTILES ? sms : NTILES;

    cudaFuncSetAttribute(gemm_hmma_kernel, cudaFuncAttributeMaxDynamicSharedMemorySize,
                         (int)SMEM_BYTES);
    gemm_hmma_kernel<<<grid, 256, SMEM_BYTES>>>(b, out);
}

// round 10
// speedup vs baseline: 1.2390x; 1.2390x over previous
#include <cuda_runtime.h>
#include <cuda_fp16.h>
#include <cstdint>

// ============================================================================
// out[8192,4096] = x[8192,4096] @ W[4096(k),4096(n)] + b
// sm_103 base-ISA: cp.async 4-stage + ldmatrix + mma.sync.m16n8k16 (fp32 acc)
// R10: persistent CTAs with R8's EXACT inner loop. Outer loop over tiles;
//      per-tile constants hoisted; ring phase continuous (NK % STAGES == 0).
//      R9's regression was dynamic per-slab indexing — removed.
// ============================================================================

static constexpr int BATCH = 8192;
static constexpr int IN_F  = 4096;   // K
static constexpr int OUT_F = 4096;   // N

static constexpr int TM = 128;
static constexpr int TN = 256;
static constexpr int KS = 64;              // K per stage (128B rows)
static constexpr int NK = IN_F / KS;       // 64 slabs per tile (NK % STAGES == 0)
static constexpr int NTILES = (BATCH / TM) * (OUT_F / TN);   // 1024
static constexpr int STAGES = 4;

static constexpr uint32_t A_ST = TM * 128u;                 // 16 KB
static constexpr uint32_t B_ST = TN * 128u;                 // 32 KB
static constexpr uint32_t STAGE = A_ST + B_ST;              // 48 KB
static constexpr uint32_t SMEM_BYTES = 1024u + STAGES * STAGE;

__device__ __align__(128) __half g_xh[(size_t)BATCH * IN_F];  // x fp16 [M,K]
__device__ __align__(128) __half g_wt[(size_t)OUT_F * IN_F];  // W^T fp16 [N,K]

// ----------------------------------------------------------------------------
__device__ __forceinline__ uint32_t smem_u32(const void* p) {
    uint32_t a;
    asm("{ .reg .u64 t; cvta.to.shared.u64 t, %1; cvt.u32.u64 %0, t; }" : "=r"(a) : "l"(p));
    return a;
}
__device__ __forceinline__ uint32_t sw128(uint32_t off) {
    return off ^ ((off >> 3) & 0x70u);
}
__device__ __forceinline__ void cp16(uint32_t s, const void* g) {
    asm volatile("cp.async.cg.shared.global [%0], [%1], 16;" :: "r"(s), "l"(g));
}
__device__ __forceinline__ void ldsm4(uint32_t& r0, uint32_t& r1, uint32_t& r2, uint32_t& r3,
                                      uint32_t addr) {
    asm volatile("ldmatrix.sync.aligned.m8n8.x4.shared.b16 {%0,%1,%2,%3}, [%4];"
                 : "=r"(r0), "=r"(r1), "=r"(r2), "=r"(r3) : "r"(addr));
}
__device__ __forceinline__ void mma16816(float& c0, float& c1, float& c2, float& c3,
                                         uint32_t a0, uint32_t a1, uint32_t a2, uint32_t a3,
                                         uint32_t b0, uint32_t b1) {
    asm volatile(
        "mma.sync.aligned.m16n8k16.row.col.f32.f16.f16.f32 "
        "{%0,%1,%2,%3}, {%4,%5,%6,%7}, {%8,%9}, {%0,%1,%2,%3};"
        : "+f"(c0), "+f"(c1), "+f"(c2), "+f"(c3)
        : "r"(a0), "r"(a1), "r"(a2), "r"(a3), "r"(b0), "r"(b1));
}

// ----------------------------------------------------------------------------
// Fused preprocessing (unchanged from R8)
// ----------------------------------------------------------------------------
static constexpr int W_BLOCKS = (OUT_F / 64) * (IN_F / 64);   // 4096
static constexpr int X_BLOCKS = 4096;

__global__ void __launch_bounds__(256)
cvt_fused_kernel(const float* __restrict__ x, const float* __restrict__ w) {
    const int bid = blockIdx.x;
    if (bid < W_BLOCKS) {
        __shared__ __half tile[64][66];
        const int bx = bid & ((OUT_F / 64) - 1);
        const int by = bid >> 6;
        const int i0 = by * 64;
        const int o0 = bx * 64;
        const int tc = threadIdx.x & 63;
        const int tr = threadIdx.x >> 6;
        #pragma unroll
        for (int r = 0; r < 16; r++) {
            const int i = tr + r * 4;
            tile[i][tc] = __float2half(w[(size_t)(i0 + i) * OUT_F + o0 + tc]);
        }
        __syncthreads();
        #pragma unroll
        for (int r = 0; r < 16; r++) {
            const int o = tr + r * 4;
            g_wt[(size_t)(o0 + o) * IN_F + i0 + tc] = tile[tc][o];
        }
    } else {
        const size_t n8 = (size_t)BATCH * IN_F / 8;
        const size_t stride = (size_t)X_BLOCKS * 256;
        for (size_t i = (size_t)(bid - W_BLOCKS) * 256 + threadIdx.x; i < n8; i += stride) {
            float4 a = ((const float4*)x)[2 * i];
            float4 c = ((const float4*)x)[2 * i + 1];
            __half2 h0 = __floats2half2_rn(a.x, a.y);
            __half2 h1 = __floats2half2_rn(a.z, a.w);
            __half2 h2 = __floats2half2_rn(c.x, c.y);
            __half2 h3 = __floats2half2_rn(c.z, c.w);
            uint4 o;
            o.x = *reinterpret_cast<uint32_t*>(&h0);
            o.y = *reinterpret_cast<uint32_t*>(&h1);
            o.z = *reinterpret_cast<uint32_t*>(&h2);
            o.w = *reinterpret_cast<uint32_t*>(&h3);
            ((uint4*)g_xh)[i] = o;
        }
    }
}

// ----------------------------------------------------------------------------
// GEMM: persistent CTAs; per tile: 128x256, 256 thr, 8 warps (2Mx4N, 64x64)
// ----------------------------------------------------------------------------
__device__ __forceinline__ void load_chunk(uint32_t st, int tid,
                                           const __half* a, const __half* b, int q) {
    if (q < 4) {
        int id = tid + (q << 8);
        int row = id >> 3;
        int c = id & 7;
        uint32_t sw = sw128(((uint32_t)row << 7) | ((uint32_t)c << 4));
        cp16(st + sw, a + (size_t)row * IN_F + (c << 3));
    } else {
        int id = tid + ((q - 4) << 8);
        int row = id >> 3;
        int c = id & 7;
        uint32_t sw = sw128(((uint32_t)row << 7) | ((uint32_t)c << 4));
        cp16(st + A_ST + sw, b + (size_t)row * IN_F + (c << 3));
    }
}

__device__ __forceinline__ void tile_bases(int t_idx, const __half*& a, const __half*& b) {
    a = g_xh + (size_t)(t_idx >> 4) * TM * IN_F;
    b = g_wt + (size_t)(t_idx & 15) * TN * IN_F;
}

__global__ void __launch_bounds__(256, 1)
gemm_hmma_kernel(const float* __restrict__ bias, float* __restrict__ out) {
    extern __shared__ char smem_raw[];
    const uint32_t S0 = (smem_u32(smem_raw) + 1023u) & ~1023u;

    const int tid  = threadIdx.x;
    const int wid  = tid >> 5;
    const int lane = tid & 31;
    const int wm   = wid & 1;
    const int wn   = wid >> 1;
    const int bid  = blockIdx.x;
    const int gdim = gridDim.x;

    const uint32_t a_row  = (uint32_t)(wm * 64 + (lane & 15));
    const uint32_t a_colb = (uint32_t)((lane >> 4) << 4);
    const uint32_t b_row  = (uint32_t)(wn * 64 + ((lane >> 4) << 3) + (lane & 7));
    const uint32_t b_colb = (uint32_t)(((lane >> 3) & 1) << 4);

    float acc[4][8][4];
    #pragma unroll
    for (int t = 0; t < 4; t++)
        #pragma unroll
        for (int j = 0; j < 8; j++)
            #pragma unroll
            for (int q = 0; q < 4; q++) acc[t][j][q] = 0.0f;

    // Prologue for the FIRST tile: fill stages 0..2 with slabs 0..2
    {
        const __half *pa, *pb;
        tile_bases(bid, pa, pb);
        #pragma unroll
        for (int p = 0; p < STAGES - 1; p++) {
            #pragma unroll
            for (int q = 0; q < 12; q++)
                load_chunk(S0 + (uint32_t)p * STAGE, tid, pa + (size_t)p * KS, pb + (size_t)p * KS, q);
            asm volatile("cp.async.commit_group;" ::: "memory");
        }
    }
    asm volatile("cp.async.wait_group 1;" ::: "memory");
    __syncthreads();

    uint32_t af[2][4][4], bf[2][4][4];

    // Preload tile0 / slab0 / kk=0 fragments into buffer 0
    #pragma unroll
    for (int t = 0; t < 4; t++) {
        uint32_t off = (a_row + t * 16u) * 128u + a_colb;
        ldsm4(af[0][t][0], af[0][t][1], af[0][t][2], af[0][t][3], S0 + sw128(off));
    }
    #pragma unroll
    for (int p = 0; p < 4; p++) {
        uint32_t off = (b_row + p * 16u) * 128u + b_colb;
        ldsm4(bf[0][p][0], bf[0][p][1], bf[0][p][2], bf[0][p][3], S0 + A_ST + sw128(off));
    }

    for (int t_idx = bid; t_idx < NTILES; t_idx += gdim) {
        // Per-tile constants (hoisted out of the hot loop)
        const __half *gA, *gB, *gA2, *gB2;
        tile_bases(t_idx, gA, gB);
        const bool hasNext = (t_idx + gdim) < NTILES;
        tile_bases(hasNext ? (t_idx + gdim) : t_idx, gA2, gB2);
        const bool lastTile = !hasNext;

        for (int it = 0; it < NK; ++it) {
            const uint32_t stA = S0 + (uint32_t)(it & (STAGES - 1)) * STAGE;
            const uint32_t stB = stA + A_ST;
            const uint32_t stNext = S0 + (uint32_t)((it + 1) & (STAGES - 1)) * STAGE;
            const bool last = lastTile && (it == NK - 1);

            const int j = it + (STAGES - 1);
            const bool inTile = (j < NK);
            const bool doload = inTile || hasNext;
            const uint32_t stJ = S0 + (uint32_t)(j & (STAGES - 1)) * STAGE;
            const __half* nA = (inTile ? gA : gA2 - (size_t)NK * KS) + (size_t)j * KS;
            const __half* nB = (inTile ? gB : gB2 - (size_t)NK * KS) + (size_t)j * KS;

            #pragma unroll
            for (int kk = 0; kk < 4; kk++) {
                const int cur = kk & 1;
                const int nxt = cur ^ 1;
                // prefetch fragments: kk+1 of this slab, or kk=0 of next slab at kk=3
                if (kk < 3) {
                    const uint32_t kc = (uint32_t)((kk + 1) * 32);
                    #pragma unroll
                    for (int t = 0; t < 4; t++) {
                        uint32_t off = (a_row + t * 16u) * 128u + kc + a_colb;
                        ldsm4(af[nxt][t][0], af[nxt][t][1], af[nxt][t][2], af[nxt][t][3],
                              stA + sw128(off));
                    }
                    #pragma unroll
                    for (int p = 0; p < 4; p++) {
                        uint32_t off = (b_row + p * 16u) * 128u + kc + b_colb;
                        ldsm4(bf[nxt][p][0], bf[nxt][p][1], bf[nxt][p][2], bf[nxt][p][3],
                              stB + sw128(off));
                    }
                } else if (!last) {
                    #pragma unroll
                    for (int t = 0; t < 4; t++) {
                        uint32_t off = (a_row + t * 16u) * 128u + a_colb;
                        ldsm4(af[nxt][t][0], af[nxt][t][1], af[nxt][t][2], af[nxt][t][3],
                              stNext + sw128(off));
                    }
                    #pragma unroll
                    for (int p = 0; p < 4; p++) {
                        uint32_t off = (b_row + p * 16u) * 128u + b_colb;
                        ldsm4(bf[nxt][p][0], bf[nxt][p][1], bf[nxt][p][2], bf[nxt][p][3],
                              stNext + A_ST + sw128(off));
                    }
                }
                // spread next-slab global loads: 3 chunks per kk
                if (doload) {
                    #pragma unroll
                    for (int c = 0; c < 3; c++) load_chunk(stJ, tid, nA, nB, kk * 3 + c);
                }
                // 32 MMAs on current fragments
                #pragma unroll
                for (int t = 0; t < 4; t++) {
                    #pragma unroll
                    for (int p = 0; p < 4; p++) {
                        mma16816(acc[t][2*p][0], acc[t][2*p][1], acc[t][2*p][2], acc[t][2*p][3],
                                 af[cur][t][0], af[cur][t][1], af[cur][t][2], af[cur][t][3],
                                 bf[cur][p][0], bf[cur][p][1]);
                        mma16816(acc[t][2*p+1][0], acc[t][2*p+1][1], acc[t][2*p+1][2], acc[t][2*p+1][3],
                                 af[cur][t][0], af[cur][t][1], af[cur][t][2], af[cur][t][3],
                                 bf[cur][p][2], bf[cur][p][3]);
                    }
                }
            }
            asm volatile("cp.async.commit_group;" ::: "memory");
            if (!last) {
                asm volatile("cp.async.wait_group 1;" ::: "memory");
                __syncthreads();
            }
        }

        // Epilogue for this tile: acc + bias -> gmem, re-zero acc.
        // Next tile's stages 0..2 are already in the ring (loaded by it=61..63).
        {
            const int tile_m = t_idx >> 4;
            const int tile_n = t_idx & 15;
            const int n_base = tile_n * TN + wn * 64 + (lane & 3) * 2;
            const int m_base = tile_m * TM + wm * 64 + (lane >> 2);
            #pragma unroll
            for (int t = 0; t < 4; t++) {
                float* r0 = out + (size_t)(m_base + t * 16) * OUT_F + n_base;
                float* r1 = r0 + 8 * OUT_F;
                #pragma unroll
                for (int jj = 0; jj < 8; jj++) {
                    const float2 bv = *(const float2*)(bias + n_base + jj * 8);
                    float2 v0 = make_float2(acc[t][jj][0] + bv.x, acc[t][jj][1] + bv.y);
                    float2 v1 = make_float2(acc[t][jj][2] + bv.x, acc[t][jj][3] + bv.y);
                    *(float2*)(r0 + jj * 8) = v0;
                    *(float2*)(r1 + jj * 8) = v1;
                    acc[t][jj][0] = 0.0f; acc[t][jj][1] = 0.0f;
                    acc[t][jj][2] = 0.0f; acc[t][jj][3] = 0.0f;
                }
            }
        }
    }
}

// ----------------------------------------------------------------------------
extern "C" void kernel_launch(void* const* d_in, const int* in_sizes, int n_in,
                              void* d_out, int out_size) {
    (void)in_sizes; (void)n_in; (void)out_size;
    const float* x = (const float*)d_in[0];
    const float* w = (const float*)d_in[1];
    const float* b = (const float*)d_in[2];
    float* out = (float*)d_out;

    cvt_fused_kernel<<<W_BLOCKS + X_BLOCKS, 256>>>(x, w);

    int sms = 0;
    cudaDeviceGetAttribute(&sms, cudaDevAttrMultiProcessorCount, 0);
    if (sms <= 0) sms = 148;
    const int grid = sms < NTILES ? sms : NTILES;

    cudaFuncSetAttribute(gemm_hmma_kernel, cudaFuncAttributeMaxDynamicSharedMemorySize,
                         (int)SMEM_BYTES);
    gemm_hmma_kernel<<<grid, 256, SMEM_BYTES>>>(b, out);
}